// round 3
// baseline (speedup 1.0000x reference)
#include <cuda_runtime.h>
#include <math.h>

// Problem constants
#define B_    64
#define T_    50000
#define C_    4
#define MS_   4
#define D_    160
#define P_    25
#define L_    2000        // T_/P_

// Kernel 1 (frontend) config
#define TILE_T 2500
#define NT1    256
#define TILES_PER_B 20    // 50000/2500
#define XB_STRIDE (TILE_T + 32)   // halo 16 each side
#define S0_STRIDE (TILE_T + 8)    // halo 4 each side

// Kernel 2 (patch GEMM + LN) config
#define PB     80         // patches per block
#define NT2    512
#define CHUNKS 25         // 2000/80
#define WP_STRIDE 164     // padded [k][d] row stride

// xs scratch: [b][m][t]  (51.2 MB, static device array — allocation-free)
__device__ float g_xs[(size_t)B_ * MS_ * T_];

__device__ __forceinline__ float gelu_f(float x) {
    return 0.5f * x * (1.0f + erff(x * 0.70710678118654752f));
}
__device__ __forceinline__ float wsum(float v) {
#pragma unroll
    for (int o = 16; o > 0; o >>= 1) v += __shfl_xor_sync(0xffffffffu, v, o);
    return v;
}

// ---------------------------------------------------------------------------
// K1: fused frontend. Per block: one batch b, one tile of 2500 timesteps.
//   x = X*M -> env (K=25 conv of |x|), burst (K=9 conv of |dx|),
//   xm = .9 env + .6 burst + .2 x, S0 = W @ xm (W = norm softplus)
//   *** S0 is zeroed outside global t in [0,T): the reference zero-pads S
//       for the w_pre_dw conv; it does NOT evaluate S at padded x. ***
//   S1 = gelu(dwconv K=9), S2 = gelu(4x4 pw), xs = S2 * Sm
//   Sm from 4-bit M>0 mask via 16-entry table. Also writes m_patch.
// ---------------------------------------------------------------------------
__global__ __launch_bounds__(NT1) void k_frontend(
    const float* __restrict__ X, const float* __restrict__ Mw,
    const float* __restrict__ w_env, const float* __restrict__ w_burst,
    const float* __restrict__ syn, const float* __restrict__ w_pre_dw,
    const float* __restrict__ w_pre_pw, float* __restrict__ m_patch)
{
    extern __shared__ char smem_raw[];
    float* xb  = (float*)smem_raw;                        // [4][XB_STRIDE] x = X*M
    float* adx = xb + 4 * XB_STRIDE;                      // [4][XB_STRIDE] guarded |dx|
    float* s0  = adx + 4 * XB_STRIDE;                     // [4][S0_STRIDE]
    unsigned char* mk = (unsigned char*)(s0 + 4 * S0_STRIDE); // [2500] (pad 2512)
    float* wenv  = (float*)(mk + 2512);                   // [4][25]
    float* wbur  = wenv + 100;                            // [4][9]
    float* wdw   = wbur + 36;                             // [4][9]
    float* pw    = wdw + 36;                              // [4][4]
    float* Wmc   = pw + 16;                               // [4][4]
    float* smtab = Wmc + 16;                              // [16][4]

    const int tid  = threadIdx.x;
    const int tile = blockIdx.x;
    const int b    = blockIdx.y;
    const int t0   = tile * TILE_T;

    // small weights (disjoint thread ranges)
    if (tid < 100)                  wenv[tid]      = w_env[tid];
    if (tid >= 128 && tid < 164)    wbur[tid-128]  = w_burst[tid-128];
    if (tid >= 164 && tid < 200)    wdw[tid-164]   = w_pre_dw[tid-164];
    if (tid >= 200 && tid < 216)    pw[tid-200]    = w_pre_pw[tid-200];
    if (tid >= 216 && tid < 220) {
        int m = tid - 216;
        float w0 = log1pf(expf(syn[m*4+0]));
        float w1 = log1pf(expf(syn[m*4+1]));
        float w2 = log1pf(expf(syn[m*4+2]));
        float w3 = log1pf(expf(syn[m*4+3]));
        float inv = 1.0f / fmaxf(w0+w1+w2+w3, 1e-6f);
        Wmc[m*4+0] = w0*inv; Wmc[m*4+1] = w1*inv;
        Wmc[m*4+2] = w2*inv; Wmc[m*4+3] = w3*inv;
    }

    // load x = X*M (halo 16) + channel mask (tile region only, always in-range)
    const float4* X4 = (const float4*)X;
    const float4* M4 = (const float4*)Mw;
    for (int i = tid; i < TILE_T + 32; i += NT1) {
        int gt = t0 - 16 + i;
        float4 v = make_float4(0.f, 0.f, 0.f, 0.f);
        if (gt >= 0 && gt < T_) {
            float4 xv = X4[b * T_ + gt];
            float4 mv = M4[b * T_ + gt];
            v.x = xv.x*mv.x; v.y = xv.y*mv.y; v.z = xv.z*mv.z; v.w = xv.w*mv.w;
            if (i >= 16 && i < 16 + TILE_T)
                mk[i-16] = (unsigned char)((mv.x > 0.f)       | ((mv.y > 0.f) << 1) |
                                           ((mv.z > 0.f) << 2)| ((mv.w > 0.f) << 3));
        }
        xb[0*XB_STRIDE + i] = v.x; xb[1*XB_STRIDE + i] = v.y;
        xb[2*XB_STRIDE + i] = v.z; xb[3*XB_STRIDE + i] = v.w;
    }
    __syncthreads();

    // Sm lookup table (W strictly positive; Sm = clip(sum_c W[m,c]*mm[c]))
    if (tid < 16) {
        int q = tid;
#pragma unroll
        for (int m = 0; m < 4; m++) {
            float s = 0.f;
#pragma unroll
            for (int c = 0; c < 4; c++) s += ((q >> c) & 1) ? Wmc[m*4+c] : 0.f;
            smtab[q*4 + m] = fminf(fmaxf(s, 0.f), 1.f);
        }
    }

    // guarded |dx| precompute: dx[gt] = x[gt]-x[gt-1] valid only for 1<=gt<T
    for (int i = tid; i < TILE_T + 32; i += NT1) {
        int gt = t0 - 16 + i;
        bool ok = (i >= 1) && (gt >= 1) && (gt < T_);
#pragma unroll
        for (int c = 0; c < 4; c++) {
            float d = ok ? fabsf(xb[c*XB_STRIDE + i] - xb[c*XB_STRIDE + i - 1]) : 0.f;
            adx[c*XB_STRIDE + i] = d;
        }
    }
    __syncthreads();

    // Stage B: env/burst/xm -> S0[m][j], j in [0, TILE_T+8), global t = t0+j-4
    for (int j = tid; j < TILE_T + 8; j += NT1) {
        const int gS = t0 + j - 4;
        if (gS < 0 || gS >= T_) {
            // reference zero-pads S for the pre_dw conv
            s0[0*S0_STRIDE + j] = 0.f; s0[1*S0_STRIDE + j] = 0.f;
            s0[2*S0_STRIDE + j] = 0.f; s0[3*S0_STRIDE + j] = 0.f;
            continue;
        }
        float a0 = 0.f, a1 = 0.f, a2 = 0.f, a3 = 0.f;
        const int ci = j + 12;   // xb index of this timestep
#pragma unroll
        for (int c = 0; c < 4; c++) {
            const float* xc = xb  + c * XB_STRIDE;
            const float* dc = adx + c * XB_STRIDE;
            float env = 0.f;
#pragma unroll
            for (int k = 0; k < 25; k++) env += wenv[c*25+k] * fabsf(xc[j+k]);
            float burst = 0.f;
#pragma unroll
            for (int k = 0; k < 9; k++) burst += wbur[c*9+k] * dc[j+8+k];
            float xm = 0.9f*env + 0.6f*burst + 0.2f*xc[ci];
            a0 += Wmc[0*4+c]*xm; a1 += Wmc[1*4+c]*xm;
            a2 += Wmc[2*4+c]*xm; a3 += Wmc[3*4+c]*xm;
        }
        s0[0*S0_STRIDE + j] = a0; s0[1*S0_STRIDE + j] = a1;
        s0[2*S0_STRIDE + j] = a2; s0[3*S0_STRIDE + j] = a3;
    }
    __syncthreads();

    // Stage C: dwconv+gelu, pw+gelu, Sm gate -> g_xs
    for (int t = tid; t < TILE_T; t += NT1) {
        float s1[4];
#pragma unroll
        for (int m = 0; m < 4; m++) {
            const float* sm = s0 + m * S0_STRIDE;
            float a = 0.f;
#pragma unroll
            for (int k = 0; k < 9; k++) a += wdw[m*9+k] * sm[t + k];
            s1[m] = gelu_f(a);
        }
        const int q = mk[t];
#pragma unroll
        for (int o = 0; o < 4; o++) {
            float a = pw[o*4+0]*s1[0] + pw[o*4+1]*s1[1] +
                      pw[o*4+2]*s1[2] + pw[o*4+3]*s1[3];
            g_xs[((size_t)(b*4 + o)) * T_ + t0 + t] = gelu_f(a) * smtab[q*4 + o];
        }
    }

    // m_patch: m_time = (mask != 0); patch mean > 0.1 <=> count >= 3
    for (int pl = tid; pl < TILE_T / P_; pl += NT1) {
        int cnt = 0;
#pragma unroll
        for (int p = 0; p < 25; p++) cnt += (mk[pl*25 + p] != 0);
        m_patch[b * L_ + tile * (TILE_T / P_) + pl] = (cnt > 2) ? 1.f : 0.f;
    }
}

// ---------------------------------------------------------------------------
// K2: patch projection GEMM (160 x 80patches, K=100) + LayerNorm(160).
// w_proj staged in smem as [k][d] (stride 164); xs tile [4][2000];
// per-thread register tile: 8 d x 4 patches; then warp-per-patch LN.
// ---------------------------------------------------------------------------
__global__ __launch_bounds__(NT2) void k_gemm_ln(
    const float* __restrict__ w_proj, const float* __restrict__ gamma,
    const float* __restrict__ beta, float* __restrict__ out)
{
    extern __shared__ char smem_raw[];
    float* wp = (float*)smem_raw;          // [100][WP_STRIDE]
    float* xs = wp + 100 * WP_STRIDE;      // [4][2000]
    float* hs = xs + 4 * PB * P_;          // [80][160]
    float* gs = hs + PB * D_;              // [160]
    float* bs = gs + D_;                   // [160]

    const int tid   = threadIdx.x;
    const int chunk = blockIdx.x;
    const int b     = blockIdx.y;
    const int t0    = chunk * (PB * P_);

    // stage w_proj: global [d][m][p] -> smem [k][d], k = m*25+p
    for (int j = tid; j < D_ * 100; j += NT2) {
        int d = j / 100, k = j - d * 100;
        wp[k * WP_STRIDE + d] = w_proj[j];
    }
    // stage xs tile (coalesced per m)
    for (int i = tid; i < 4 * PB * P_; i += NT2) {
        int m = i / (PB * P_), t = i - m * (PB * P_);
        xs[i] = g_xs[((size_t)(b*4 + m)) * T_ + t0 + t];
    }
    if (tid < D_) { gs[tid] = gamma[tid]; bs[tid] = beta[tid]; }
    __syncthreads();

    // GEMM: 400 active threads, tid = pg*20 + dg
    if (tid < 400) {
        const int pg = tid / 20, dg = tid % 20;
        const int d0 = dg * 8;
        const int l0 = pg * 4;
        float acc[4][8];
#pragma unroll
        for (int j = 0; j < 4; j++)
#pragma unroll
            for (int i = 0; i < 8; i++) acc[j][i] = 0.f;

#pragma unroll
        for (int m = 0; m < 4; m++) {
            const float* xsm = xs + m * (PB * P_) + l0 * P_;
#pragma unroll 5
            for (int p = 0; p < 25; p++) {
                const int k = m * 25 + p;
                float4 w0 = *(const float4*)(wp + k * WP_STRIDE + d0);
                float4 w1 = *(const float4*)(wp + k * WP_STRIDE + d0 + 4);
#pragma unroll
                for (int j = 0; j < 4; j++) {
                    float v = xsm[j * P_ + p];
                    acc[j][0] += v * w0.x; acc[j][1] += v * w0.y;
                    acc[j][2] += v * w0.z; acc[j][3] += v * w0.w;
                    acc[j][4] += v * w1.x; acc[j][5] += v * w1.y;
                    acc[j][6] += v * w1.z; acc[j][7] += v * w1.w;
                }
            }
        }
#pragma unroll
        for (int j = 0; j < 4; j++) {
            float4* dst = (float4*)(hs + (l0 + j) * D_ + d0);
            dst[0] = make_float4(acc[j][0], acc[j][1], acc[j][2], acc[j][3]);
            dst[1] = make_float4(acc[j][4], acc[j][5], acc[j][6], acc[j][7]);
        }
    }
    __syncthreads();

    // LayerNorm: one warp per patch (16 warps x 5 rounds)
    const int wid = tid >> 5, lane = tid & 31;
    for (int l = wid; l < PB; l += NT2 / 32) {
        float v[5]; float s = 0.f;
#pragma unroll
        for (int r = 0; r < 5; r++) { v[r] = hs[l * D_ + lane + 32*r]; s += v[r]; }
        s = wsum(s);
        float mu = s * (1.0f / 160.0f);
        float var = 0.f;
#pragma unroll
        for (int r = 0; r < 5; r++) { float d = v[r] - mu; var += d * d; }
        var = wsum(var);
        float inv = rsqrtf(var * (1.0f / 160.0f) + 1e-5f);
        size_t base = ((size_t)(b * L_) + chunk * PB + l) * D_;
#pragma unroll
        for (int r = 0; r < 5; r++) {
            int d = lane + 32*r;
            out[base + d] = (v[r] - mu) * inv * gs[d] + bs[d];
        }
    }
}

// ---------------------------------------------------------------------------
extern "C" void kernel_launch(void* const* d_in, const int* in_sizes, int n_in,
                              void* d_out, int out_size)
{
    (void)in_sizes; (void)n_in; (void)out_size;
    const float* X        = (const float*)d_in[0];
    const float* Mw       = (const float*)d_in[1];
    const float* w_env    = (const float*)d_in[2];
    const float* w_burst  = (const float*)d_in[3];
    const float* syn      = (const float*)d_in[4];
    const float* w_pre_dw = (const float*)d_in[5];
    const float* w_pre_pw = (const float*)d_in[6];
    const float* w_proj   = (const float*)d_in[7];
    const float* gamma    = (const float*)d_in[8];
    const float* beta     = (const float*)d_in[9];

    float* out     = (float*)d_out;
    float* m_patch = out + (size_t)B_ * L_ * D_;   // h first, then m_patch

    const size_t smem1 = (8 * XB_STRIDE + 4 * S0_STRIDE) * sizeof(float)
                         + 2512 + 268 * sizeof(float);
    const size_t smem2 = (100 * WP_STRIDE + 4 * PB * P_ + PB * D_ + 2 * D_)
                         * sizeof(float);

    cudaFuncSetAttribute(k_frontend, cudaFuncAttributeMaxDynamicSharedMemorySize,
                         (int)smem1);
    cudaFuncSetAttribute(k_gemm_ln, cudaFuncAttributeMaxDynamicSharedMemorySize,
                         (int)smem2);

    dim3 g1(TILES_PER_B, B_);
    dim3 g2(CHUNKS, B_);
    k_frontend<<<g1, NT1, smem1>>>(X, Mw, w_env, w_burst, syn,
                                   w_pre_dw, w_pre_pw, m_patch);
    k_gemm_ln<<<g2, NT2, smem2>>>(w_proj, gamma, beta, out);
}

// round 7
// speedup vs baseline: 1.3500x; 1.3500x over previous
#include <cuda_runtime.h>
#include <math.h>

// Problem constants
#define B_    64
#define T_    50000
#define C_    4
#define MS_   4
#define D_    160
#define P_    25
#define L_    2000        // T_/P_

// Kernel 1 (frontend) config
#define TILE_T 2500
#define NT1    512
#define TILES_PER_B 20    // 50000/2500
#define XB_STRIDE (TILE_T + 32)   // halo 16 each side
#define S0_STRIDE (TILE_T + 8)    // halo 4 each side

// Kernel 2 (patch GEMM + LN) config
#define PB     80         // patches per block
#define NT2    512
#define CHUNKS 25         // 2000/80
#define WP_STRIDE 164     // padded [k][d] row stride

// xs scratch: [b][m][t]  (51.2 MB, static device array — allocation-free)
__device__ float g_xs[(size_t)B_ * MS_ * T_];

__device__ __forceinline__ float gelu_f(float x) {
    return 0.5f * x * (1.0f + erff(x * 0.70710678118654752f));
}

// ---------------------------------------------------------------------------
// K1: fused frontend. Per block: one batch b, one tile of 2500 timesteps.
//   x = X*M -> env (K=25 conv of |x|), burst (K=9 conv of |dx|),
//   xm = .9 env + .6 burst + .2 x, S0 = W @ xm (W = norm softplus)
//   S0 zeroed outside global t in [0,T) (reference zero-pads S, not re-evals).
//   S1 = gelu(dwconv K=9), S2 = gelu(4x4 pw), xs = S2 * Sm.
//   |dx| recomputed inline (fast path for interior t) to keep smem at 84KB
//   -> 2 CTAs/SM at 512 threads.
// ---------------------------------------------------------------------------
__global__ __launch_bounds__(NT1, 2) void k_frontend(
    const float* __restrict__ X, const float* __restrict__ Mw,
    const float* __restrict__ w_env, const float* __restrict__ w_burst,
    const float* __restrict__ syn, const float* __restrict__ w_pre_dw,
    const float* __restrict__ w_pre_pw, float* __restrict__ m_patch)
{
    extern __shared__ char smem_raw[];
    float* xb  = (float*)smem_raw;                        // [4][XB_STRIDE] x = X*M
    float* s0  = xb + 4 * XB_STRIDE;                      // [4][S0_STRIDE]
    unsigned char* mk = (unsigned char*)(s0 + 4 * S0_STRIDE); // [2500] (pad 2512)
    float* wenv  = (float*)(mk + 2512);                   // [4][25]
    float* wbur  = wenv + 100;                            // [4][9]
    float* wdw   = wbur + 36;                             // [4][9]
    float* pw    = wdw + 36;                              // [4][4]
    float* Wmc   = pw + 16;                               // [4][4]
    float* smtab = Wmc + 16;                              // [16][4]

    const int tid  = threadIdx.x;
    const int tile = blockIdx.x;
    const int b    = blockIdx.y;
    const int t0   = tile * TILE_T;

    // small weights (disjoint thread ranges)
    if (tid < 100)                  wenv[tid]      = w_env[tid];
    if (tid >= 128 && tid < 164)    wbur[tid-128]  = w_burst[tid-128];
    if (tid >= 164 && tid < 200)    wdw[tid-164]   = w_pre_dw[tid-164];
    if (tid >= 200 && tid < 216)    pw[tid-200]    = w_pre_pw[tid-200];
    if (tid >= 216 && tid < 220) {
        int m = tid - 216;
        float w0 = log1pf(expf(syn[m*4+0]));
        float w1 = log1pf(expf(syn[m*4+1]));
        float w2 = log1pf(expf(syn[m*4+2]));
        float w3 = log1pf(expf(syn[m*4+3]));
        float inv = 1.0f / fmaxf(w0+w1+w2+w3, 1e-6f);
        Wmc[m*4+0] = w0*inv; Wmc[m*4+1] = w1*inv;
        Wmc[m*4+2] = w2*inv; Wmc[m*4+3] = w3*inv;
    }

    // load x = X*M (halo 16) + channel mask (tile region only, always in-range)
    const float4* X4 = (const float4*)X;
    const float4* M4 = (const float4*)Mw;
    for (int i = tid; i < TILE_T + 32; i += NT1) {
        int gt = t0 - 16 + i;
        float4 v = make_float4(0.f, 0.f, 0.f, 0.f);
        if (gt >= 0 && gt < T_) {
            float4 xv = X4[b * T_ + gt];
            float4 mv = M4[b * T_ + gt];
            v.x = xv.x*mv.x; v.y = xv.y*mv.y; v.z = xv.z*mv.z; v.w = xv.w*mv.w;
            if (i >= 16 && i < 16 + TILE_T)
                mk[i-16] = (unsigned char)((mv.x > 0.f)       | ((mv.y > 0.f) << 1) |
                                           ((mv.z > 0.f) << 2)| ((mv.w > 0.f) << 3));
        }
        xb[0*XB_STRIDE + i] = v.x; xb[1*XB_STRIDE + i] = v.y;
        xb[2*XB_STRIDE + i] = v.z; xb[3*XB_STRIDE + i] = v.w;
    }
    __syncthreads();

    // Sm lookup table (W strictly positive; Sm = clip(sum_c W[m,c]*mm[c]))
    if (tid < 16) {
        int q = tid;
#pragma unroll
        for (int m = 0; m < 4; m++) {
            float s = 0.f;
#pragma unroll
            for (int c = 0; c < 4; c++) s += ((q >> c) & 1) ? Wmc[m*4+c] : 0.f;
            smtab[q*4 + m] = fminf(fmaxf(s, 0.f), 1.f);
        }
    }
    __syncthreads();

    // Stage B: env/burst/xm -> S0[m][j], j in [0, TILE_T+8), global t = t0+j-4
    for (int j = tid; j < TILE_T + 8; j += NT1) {
        const int gS = t0 + j - 4;
        if (gS < 0 || gS >= T_) {
            // reference zero-pads S for the pre_dw conv
            s0[0*S0_STRIDE + j] = 0.f; s0[1*S0_STRIDE + j] = 0.f;
            s0[2*S0_STRIDE + j] = 0.f; s0[3*S0_STRIDE + j] = 0.f;
            continue;
        }
        float a0 = 0.f, a1 = 0.f, a2 = 0.f, a3 = 0.f;
        const int ci = j + 12;   // xb index of this timestep
        const bool interior = (gS >= 5) && (gS <= T_ - 5);
#pragma unroll
        for (int c = 0; c < 4; c++) {
            const float* xc = xb + c * XB_STRIDE;
            float env = 0.f;
#pragma unroll
            for (int k = 0; k < 25; k++) env += wenv[c*25+k] * fabsf(xc[j+k]);
            float burst = 0.f;
            if (interior) {
#pragma unroll
                for (int k = 0; k < 9; k++) {
                    int ii = j + 8 + k;
                    burst += wbur[c*9+k] * fabsf(xc[ii] - xc[ii-1]);
                }
            } else {
#pragma unroll
                for (int k = 0; k < 9; k++) {
                    int ii = j + 8 + k;
                    int gt = gS - 4 + k;           // global t of the dx sample
                    float dxv = (gt >= 1 && gt < T_) ? fabsf(xc[ii] - xc[ii-1]) : 0.f;
                    burst += wbur[c*9+k] * dxv;
                }
            }
            float xm = 0.9f*env + 0.6f*burst + 0.2f*xc[ci];
            a0 += Wmc[0*4+c]*xm; a1 += Wmc[1*4+c]*xm;
            a2 += Wmc[2*4+c]*xm; a3 += Wmc[3*4+c]*xm;
        }
        s0[0*S0_STRIDE + j] = a0; s0[1*S0_STRIDE + j] = a1;
        s0[2*S0_STRIDE + j] = a2; s0[3*S0_STRIDE + j] = a3;
    }
    __syncthreads();

    // Stage C: dwconv+gelu, pw+gelu, Sm gate -> g_xs
    for (int t = tid; t < TILE_T; t += NT1) {
        float s1[4];
#pragma unroll
        for (int m = 0; m < 4; m++) {
            const float* sm = s0 + m * S0_STRIDE;
            float a = 0.f;
#pragma unroll
            for (int k = 0; k < 9; k++) a += wdw[m*9+k] * sm[t + k];
            s1[m] = gelu_f(a);
        }
        const int q = mk[t];
#pragma unroll
        for (int o = 0; o < 4; o++) {
            float a = pw[o*4+0]*s1[0] + pw[o*4+1]*s1[1] +
                      pw[o*4+2]*s1[2] + pw[o*4+3]*s1[3];
            g_xs[((size_t)(b*4 + o)) * T_ + t0 + t] = gelu_f(a) * smtab[q*4 + o];
        }
    }

    // m_patch: m_time = (mask != 0); patch mean > 0.1 <=> count >= 3
    for (int pl = tid; pl < TILE_T / P_; pl += NT1) {
        int cnt = 0;
#pragma unroll
        for (int p = 0; p < 25; p++) cnt += (mk[pl*25 + p] != 0);
        m_patch[b * L_ + tile * (TILE_T / P_) + pl] = (cnt > 2) ? 1.f : 0.f;
    }
}

// ---------------------------------------------------------------------------
// K2: patch projection GEMM (160 x 80patches, K=100) + LayerNorm(160).
// w_proj staged in smem as [k][d] (stride 164); xs tile [4][2000];
// per-thread register tile: 8 d x 4 patches. LN stats via two-pass
// deterministic 20-way tree reduction in smem; acc normalized in registers
// and stored straight to gmem (no hs buffer -> 112KB smem -> 2 CTAs/SM).
// ---------------------------------------------------------------------------
__global__ __launch_bounds__(NT2, 2) void k_gemm_ln(
    const float* __restrict__ w_proj, const float* __restrict__ gamma,
    const float* __restrict__ beta, float* __restrict__ out)
{
    extern __shared__ char smem_raw[];
    float* wp   = (float*)smem_raw;        // [100][WP_STRIDE]  65.6KB
    float* xs   = wp + 100 * WP_STRIDE;    // [4][2000]         32KB
    float* red  = xs + 4 * PB * P_;        // [80][20]          6.4KB
    float* mus  = red + PB * 20;           // [80]
    float* invs = mus + PB;                // [80]
    float* gs   = invs + PB;               // [160]
    float* bs   = gs + D_;                 // [160]

    const int tid   = threadIdx.x;
    const int chunk = blockIdx.x;
    const int b     = blockIdx.y;
    const int t0    = chunk * (PB * P_);

    // stage w_proj: global [d][m][p] -> smem [k][d], k = m*25+p
    for (int j = tid; j < D_ * 100; j += NT2) {
        int d = j / 100, k = j - d * 100;
        wp[k * WP_STRIDE + d] = w_proj[j];
    }
    // stage xs tile (coalesced per m)
    for (int i = tid; i < 4 * PB * P_; i += NT2) {
        int m = i / (PB * P_), t = i - m * (PB * P_);
        xs[i] = g_xs[((size_t)(b*4 + m)) * T_ + t0 + t];
    }
    if (tid < D_) { gs[tid] = gamma[tid]; bs[tid] = beta[tid]; }
    __syncthreads();

    // GEMM: 400 active threads, tid = pg*20 + dg
    const int pg = tid / 20, dg = tid % 20;
    const int d0 = dg * 8;
    const int l0 = pg * 4;
    const bool active = (tid < 400);
    float acc[4][8];
#pragma unroll
    for (int j = 0; j < 4; j++)
#pragma unroll
        for (int i = 0; i < 8; i++) acc[j][i] = 0.f;

    if (active) {
#pragma unroll
        for (int m = 0; m < 4; m++) {
            const float* xsm = xs + m * (PB * P_) + l0 * P_;
#pragma unroll 5
            for (int p = 0; p < 25; p++) {
                const int k = m * 25 + p;
                float4 w0 = *(const float4*)(wp + k * WP_STRIDE + d0);
                float4 w1 = *(const float4*)(wp + k * WP_STRIDE + d0 + 4);
#pragma unroll
                for (int j = 0; j < 4; j++) {
                    float v = xsm[j * P_ + p];
                    acc[j][0] += v * w0.x; acc[j][1] += v * w0.y;
                    acc[j][2] += v * w0.z; acc[j][3] += v * w0.w;
                    acc[j][4] += v * w1.x; acc[j][5] += v * w1.y;
                    acc[j][6] += v * w1.z; acc[j][7] += v * w1.w;
                }
            }
        }
        // pass 1: per-thread sums -> 20 partials per patch
#pragma unroll
        for (int j = 0; j < 4; j++) {
            float s = 0.f;
#pragma unroll
            for (int i = 0; i < 8; i++) s += acc[j][i];
            red[(l0 + j) * 20 + dg] = s;
        }
    }
    __syncthreads();
    if (tid < PB) {
        float s = 0.f;
#pragma unroll
        for (int i = 0; i < 20; i++) s += red[tid * 20 + i];
        mus[tid] = s * (1.0f / 160.0f);
    }
    __syncthreads();
    // pass 2: centered sum of squares (matches reference's two-pass variance)
    if (active) {
#pragma unroll
        for (int j = 0; j < 4; j++) {
            float mu = mus[l0 + j];
            float q = 0.f;
#pragma unroll
            for (int i = 0; i < 8; i++) { float d = acc[j][i] - mu; q += d * d; }
            red[(l0 + j) * 20 + dg] = q;
        }
    }
    __syncthreads();
    if (tid < PB) {
        float q = 0.f;
#pragma unroll
        for (int i = 0; i < 20; i++) q += red[tid * 20 + i];
        invs[tid] = rsqrtf(q * (1.0f / 160.0f) + 1e-5f);
    }
    __syncthreads();

    // normalize in registers, store straight to gmem (coalesced across dg)
    if (active) {
#pragma unroll
        for (int j = 0; j < 4; j++) {
            float mu = mus[l0 + j], iv = invs[l0 + j];
            size_t base = ((size_t)(b * L_) + chunk * PB + l0 + j) * D_ + d0;
            float4 o0, o1;
            o0.x = (acc[j][0]-mu)*iv*gs[d0+0] + bs[d0+0];
            o0.y = (acc[j][1]-mu)*iv*gs[d0+1] + bs[d0+1];
            o0.z = (acc[j][2]-mu)*iv*gs[d0+2] + bs[d0+2];
            o0.w = (acc[j][3]-mu)*iv*gs[d0+3] + bs[d0+3];
            o1.x = (acc[j][4]-mu)*iv*gs[d0+4] + bs[d0+4];
            o1.y = (acc[j][5]-mu)*iv*gs[d0+5] + bs[d0+5];
            o1.z = (acc[j][6]-mu)*iv*gs[d0+6] + bs[d0+6];
            o1.w = (acc[j][7]-mu)*iv*gs[d0+7] + bs[d0+7];
            *(float4*)(out + base)     = o0;
            *(float4*)(out + base + 4) = o1;
        }
    }
}

// ---------------------------------------------------------------------------
extern "C" void kernel_launch(void* const* d_in, const int* in_sizes, int n_in,
                              void* d_out, int out_size)
{
    (void)in_sizes; (void)n_in; (void)out_size;
    const float* X        = (const float*)d_in[0];
    const float* Mw       = (const float*)d_in[1];
    const float* w_env    = (const float*)d_in[2];
    const float* w_burst  = (const float*)d_in[3];
    const float* syn      = (const float*)d_in[4];
    const float* w_pre_dw = (const float*)d_in[5];
    const float* w_pre_pw = (const float*)d_in[6];
    const float* w_proj   = (const float*)d_in[7];
    const float* gamma    = (const float*)d_in[8];
    const float* beta     = (const float*)d_in[9];

    float* out     = (float*)d_out;
    float* m_patch = out + (size_t)B_ * L_ * D_;   // h first, then m_patch

    const size_t smem1 = (4 * XB_STRIDE + 4 * S0_STRIDE) * sizeof(float)
                         + 2512 + 268 * sizeof(float);
    const size_t smem2 = (100 * WP_STRIDE + 4 * PB * P_ + PB * 20 + 2 * PB
                          + 2 * D_) * sizeof(float);

    cudaFuncSetAttribute(k_frontend, cudaFuncAttributeMaxDynamicSharedMemorySize,
                         (int)smem1);
    cudaFuncSetAttribute(k_gemm_ln, cudaFuncAttributeMaxDynamicSharedMemorySize,
                         (int)smem2);

    dim3 g1(TILES_PER_B, B_);
    dim3 g2(CHUNKS, B_);
    k_frontend<<<g1, NT1, smem1>>>(X, Mw, w_env, w_burst, syn,
                                   w_pre_dw, w_pre_pw, m_patch);
    k_gemm_ln<<<g2, NT2, smem2>>>(w_proj, gamma, beta, out);
}

// round 10
// speedup vs baseline: 1.5451x; 1.1445x over previous
#include <cuda_runtime.h>
#include <math.h>

// Problem constants
#define B_    64
#define T_    50000
#define C_    4
#define MS_   4
#define D_    160
#define P_    25
#define L_    2000        // T_/P_

// Kernel 1 (frontend) config
#define TILE_T 2500
#define NT1    512
#define TILES_PER_B 20    // 50000/2500
#define XB_STRIDE (TILE_T + 32)   // halo 16 each side (2532, %4==0)
#define S0_STRIDE (TILE_T + 8)    // halo 4 each side (2508, %4==0)

// Kernel 2 (patch GEMM + LN) config
#define PB     80         // patches per block
#define NT2    512
#define CHUNKS 25         // 2000/80
#define WP_STRIDE 164     // padded [k][d] row stride

// xs scratch: [b][m][t]  (51.2 MB, static device array — allocation-free)
__device__ float g_xs[(size_t)B_ * MS_ * T_];

__device__ __forceinline__ float gelu_f(float x) {
    return 0.5f * x * (1.0f + erff(x * 0.70710678118654752f));
}

// packed f32x2 helpers (sm_103a)
#define FMA_F32X2(acc, a, b) \
    asm("fma.rn.f32x2 %0, %1, %2, %0;" : "+l"(acc) : "l"(a), "l"(b))
#define DUP_F32X2(out, v) do {                                        \
    unsigned int _u = __float_as_uint(v);                             \
    asm("mov.b64 %0, {%1, %1};" : "=l"(out) : "r"(_u));               \
} while (0)
#define UNPACK_F32X2(lo, hi, in) do {                                 \
    unsigned int _a, _b;                                              \
    asm("mov.b64 {%0, %1}, %2;" : "=r"(_a), "=r"(_b) : "l"(in));      \
    lo = __uint_as_float(_a); hi = __uint_as_float(_b);               \
} while (0)

// ---------------------------------------------------------------------------
// K1: fused frontend. Per block: one batch b, one tile of 2500 timesteps.
// Stage B register-blocked: 2 consecutive outputs/thread, window in regs via
// float2 loads. Stage C register-blocked: 4 outputs/thread, float4 loads and
// float4 stores to g_xs.
// ---------------------------------------------------------------------------
__global__ __launch_bounds__(NT1, 2) void k_frontend(
    const float* __restrict__ X, const float* __restrict__ Mw,
    const float* __restrict__ w_env, const float* __restrict__ w_burst,
    const float* __restrict__ syn, const float* __restrict__ w_pre_dw,
    const float* __restrict__ w_pre_pw, float* __restrict__ m_patch)
{
    extern __shared__ char smem_raw[];
    float* xb  = (float*)smem_raw;                        // [4][XB_STRIDE] x = X*M
    float* s0  = xb + 4 * XB_STRIDE;                      // [4][S0_STRIDE]
    unsigned char* mk = (unsigned char*)(s0 + 4 * S0_STRIDE); // [2500] (pad 2512)
    float* wenv  = (float*)(mk + 2512);                   // [4][25]
    float* wbur  = wenv + 100;                            // [4][9]
    float* wdw   = wbur + 36;                             // [4][9]
    float* pw    = wdw + 36;                              // [4][4]
    float* Wmc   = pw + 16;                               // [4][4]
    float* smtab = Wmc + 16;                              // [16][4]

    const int tid  = threadIdx.x;
    const int tile = blockIdx.x;
    const int b    = blockIdx.y;
    const int t0   = tile * TILE_T;

    // small weights (disjoint thread ranges)
    if (tid < 100)                  wenv[tid]      = w_env[tid];
    if (tid >= 128 && tid < 164)    wbur[tid-128]  = w_burst[tid-128];
    if (tid >= 164 && tid < 200)    wdw[tid-164]   = w_pre_dw[tid-164];
    if (tid >= 200 && tid < 216)    pw[tid-200]    = w_pre_pw[tid-200];
    if (tid >= 216 && tid < 220) {
        int m = tid - 216;
        float w0 = log1pf(expf(syn[m*4+0]));
        float w1 = log1pf(expf(syn[m*4+1]));
        float w2 = log1pf(expf(syn[m*4+2]));
        float w3 = log1pf(expf(syn[m*4+3]));
        float inv = 1.0f / fmaxf(w0+w1+w2+w3, 1e-6f);
        Wmc[m*4+0] = w0*inv; Wmc[m*4+1] = w1*inv;
        Wmc[m*4+2] = w2*inv; Wmc[m*4+3] = w3*inv;
    }

    // load x = X*M (halo 16) + channel mask
    const float4* X4 = (const float4*)X;
    const float4* M4 = (const float4*)Mw;
    for (int i = tid; i < TILE_T + 32; i += NT1) {
        int gt = t0 - 16 + i;
        float4 v = make_float4(0.f, 0.f, 0.f, 0.f);
        if (gt >= 0 && gt < T_) {
            float4 xv = X4[b * T_ + gt];
            float4 mv = M4[b * T_ + gt];
            v.x = xv.x*mv.x; v.y = xv.y*mv.y; v.z = xv.z*mv.z; v.w = xv.w*mv.w;
            if (i >= 16 && i < 16 + TILE_T)
                mk[i-16] = (unsigned char)((mv.x > 0.f)       | ((mv.y > 0.f) << 1) |
                                           ((mv.z > 0.f) << 2)| ((mv.w > 0.f) << 3));
        }
        xb[0*XB_STRIDE + i] = v.x; xb[1*XB_STRIDE + i] = v.y;
        xb[2*XB_STRIDE + i] = v.z; xb[3*XB_STRIDE + i] = v.w;
    }
    __syncthreads();

    // Sm lookup table
    if (tid < 16) {
        int q = tid;
#pragma unroll
        for (int m = 0; m < 4; m++) {
            float s = 0.f;
#pragma unroll
            for (int c = 0; c < 4; c++) s += ((q >> c) & 1) ? Wmc[m*4+c] : 0.f;
            smtab[q*4 + m] = fminf(fmaxf(s, 0.f), 1.f);
        }
    }
    __syncthreads();

    // Stage B: 2 outputs per thread. Output jj at window j0: global gS = t0+j0+jj-4.
    // Window xb indices [j0, j0+25]; burst dx at xb idx ii=[j0+8, j0+17],
    // dx global t = t0 + j0 + (local) - 8, local in [0,9].
    for (int jb = tid; jb < (TILE_T + 8) / 2; jb += NT1) {
        const int j0  = jb * 2;
        const int gS0 = t0 + j0 - 4;
        const bool ok0 = (gS0 >= 0) && (gS0 < T_);
        const bool ok1 = (gS0 + 1 >= 0) && (gS0 + 1 < T_);
        float a0[4] = {0.f,0.f,0.f,0.f}, a1[4] = {0.f,0.f,0.f,0.f};
        if (ok0 | ok1) {
            const bool interior = (t0 + j0 >= 9) && (t0 + j0 + 9 < T_ + 8) &&
                                  (t0 + j0 + 1 < T_);   // all dx taps valid
#pragma unroll
            for (int c = 0; c < 4; c++) {
                const float* xc = xb + c * XB_STRIDE + j0;
                float xw[26];
#pragma unroll
                for (int i = 0; i < 13; i++) {
                    float2 v = *(const float2*)(xc + 2*i);
                    xw[2*i] = v.x; xw[2*i+1] = v.y;
                }
                // guarded |dx|, local 0..9 <-> xb idx j0+8..j0+17
                float ad[10];
                if (interior) {
#pragma unroll
                    for (int i = 0; i < 10; i++)
                        ad[i] = fabsf(xw[8+i] - xw[7+i]);
                } else {
#pragma unroll
                    for (int i = 0; i < 10; i++) {
                        int gt = t0 + j0 + i - 8;
                        ad[i] = (gt >= 1 && gt < T_) ? fabsf(xw[8+i] - xw[7+i]) : 0.f;
                    }
                }
                const float c0 = xw[12], c1 = xw[13];
#pragma unroll
                for (int i = 0; i < 26; i++) xw[i] = fabsf(xw[i]);
                float e0 = 0.f, e1 = 0.f;
#pragma unroll
                for (int k = 0; k < 25; k++) {
                    float w = wenv[c*25+k];
                    e0 += w * xw[k]; e1 += w * xw[k+1];
                }
                float bu0 = 0.f, bu1 = 0.f;
#pragma unroll
                for (int k = 0; k < 9; k++) {
                    float w = wbur[c*9+k];
                    bu0 += w * ad[k]; bu1 += w * ad[k+1];
                }
                float xm0 = 0.9f*e0 + 0.6f*bu0 + 0.2f*c0;
                float xm1 = 0.9f*e1 + 0.6f*bu1 + 0.2f*c1;
#pragma unroll
                for (int m = 0; m < 4; m++) {
                    float w = Wmc[m*4+c];
                    a0[m] += w * xm0; a1[m] += w * xm1;
                }
            }
        }
#pragma unroll
        for (int m = 0; m < 4; m++) {
            s0[m*S0_STRIDE + j0]     = ok0 ? a0[m] : 0.f;
            s0[m*S0_STRIDE + j0 + 1] = ok1 ? a1[m] : 0.f;
        }
    }
    __syncthreads();

    // Stage C: 4 outputs per thread; dwconv window [t, t+11] per m.
    for (int tb = tid; tb < TILE_T / 4; tb += NT1) {
        const int t = tb * 4;
        float s1[4][4];
#pragma unroll
        for (int m = 0; m < 4; m++) {
            const float* sm = s0 + m * S0_STRIDE + t;
            float4 v0 = *(const float4*)(sm);
            float4 v1 = *(const float4*)(sm + 4);
            float4 v2 = *(const float4*)(sm + 8);
            float sw[12] = {v0.x,v0.y,v0.z,v0.w, v1.x,v1.y,v1.z,v1.w,
                            v2.x,v2.y,v2.z,v2.w};
#pragma unroll
            for (int jj = 0; jj < 4; jj++) {
                float a = 0.f;
#pragma unroll
                for (int k = 0; k < 9; k++) a += wdw[m*9+k] * sw[jj+k];
                s1[m][jj] = gelu_f(a);
            }
        }
        const uchar4 q4 = *(const uchar4*)(mk + t);
        const int qq[4] = {q4.x, q4.y, q4.z, q4.w};
#pragma unroll
        for (int o = 0; o < 4; o++) {
            float4 r;
            float* rp = (float*)&r;
#pragma unroll
            for (int jj = 0; jj < 4; jj++) {
                float a = pw[o*4+0]*s1[0][jj] + pw[o*4+1]*s1[1][jj] +
                          pw[o*4+2]*s1[2][jj] + pw[o*4+3]*s1[3][jj];
                rp[jj] = gelu_f(a) * smtab[qq[jj]*4 + o];
            }
            *(float4*)(g_xs + ((size_t)(b*4 + o)) * T_ + t0 + t) = r;
        }
    }

    // m_patch: patch mean of (mask!=0) > 0.1 <=> count >= 3
    for (int pl = tid; pl < TILE_T / P_; pl += NT1) {
        int cnt = 0;
#pragma unroll
        for (int p = 0; p < 25; p++) cnt += (mk[pl*25 + p] != 0);
        m_patch[b * L_ + tile * (TILE_T / P_) + pl] = (cnt > 2) ? 1.f : 0.f;
    }
}

// ---------------------------------------------------------------------------
// K2: patch projection GEMM (160 x 80patches, K=100) + LayerNorm(160).
// Inner loop uses packed fma.rn.f32x2: acc pairs over adjacent d; w float4
// loads give aligned 64-bit (d,d+1) pairs for free; x duplicated via mov.b64.
// Exact fp32 arithmetic (bitwise same as scalar FFMA).
// ---------------------------------------------------------------------------
__global__ __launch_bounds__(NT2, 2) void k_gemm_ln(
    const float* __restrict__ w_proj, const float* __restrict__ gamma,
    const float* __restrict__ beta, float* __restrict__ out)
{
    extern __shared__ char smem_raw[];
    float* wp   = (float*)smem_raw;        // [100][WP_STRIDE]  65.6KB
    float* xs   = wp + 100 * WP_STRIDE;    // [4][2000]         32KB
    float* red  = xs + 4 * PB * P_;        // [80][20]          6.4KB
    float* mus  = red + PB * 20;           // [80]
    float* invs = mus + PB;                // [80]
    float* gs   = invs + PB;               // [160]
    float* bs   = gs + D_;                 // [160]

    const int tid   = threadIdx.x;
    const int chunk = blockIdx.x;
    const int b     = blockIdx.y;
    const int t0    = chunk * (PB * P_);

    // stage w_proj: global [d][m][p] -> smem [k][d], k = m*25+p
    for (int j = tid; j < D_ * 100; j += NT2) {
        int d = j / 100, k = j - d * 100;
        wp[k * WP_STRIDE + d] = w_proj[j];
    }
    // stage xs tile (coalesced per m)
    for (int i = tid; i < 4 * PB * P_; i += NT2) {
        int m = i / (PB * P_), t = i - m * (PB * P_);
        xs[i] = g_xs[((size_t)(b*4 + m)) * T_ + t0 + t];
    }
    if (tid < D_) { gs[tid] = gamma[tid]; bs[tid] = beta[tid]; }
    __syncthreads();

    // GEMM: 400 active threads, tid = pg*20 + dg
    const int pg = tid / 20, dg = tid % 20;
    const int d0 = dg * 8;
    const int l0 = pg * 4;
    const bool active = (tid < 400);

    unsigned long long acc2[4][4];   // [patch j][d-pair i] -> (d0+2i, d0+2i+1)
#pragma unroll
    for (int j = 0; j < 4; j++)
#pragma unroll
        for (int i = 0; i < 4; i++) acc2[j][i] = 0ULL;

    if (active) {
#pragma unroll
        for (int m = 0; m < 4; m++) {
            const float* xsm = xs + m * (PB * P_) + l0 * P_;
#pragma unroll 5
            for (int p = 0; p < 25; p++) {
                const int k = m * 25 + p;
                const ulonglong2 wa = *(const ulonglong2*)(wp + k * WP_STRIDE + d0);
                const ulonglong2 wb = *(const ulonglong2*)(wp + k * WP_STRIDE + d0 + 4);
#pragma unroll
                for (int j = 0; j < 4; j++) {
                    unsigned long long xd;
                    DUP_F32X2(xd, xsm[j * P_ + p]);
                    FMA_F32X2(acc2[j][0], xd, wa.x);
                    FMA_F32X2(acc2[j][1], xd, wa.y);
                    FMA_F32X2(acc2[j][2], xd, wb.x);
                    FMA_F32X2(acc2[j][3], xd, wb.y);
                }
            }
        }
    }

    // unpack accumulators
    float acc[4][8];
#pragma unroll
    for (int j = 0; j < 4; j++)
#pragma unroll
        for (int i = 0; i < 4; i++)
            UNPACK_F32X2(acc[j][2*i], acc[j][2*i+1], acc2[j][i]);

    // pass 1: per-thread sums -> 20 partials per patch
    if (active) {
#pragma unroll
        for (int j = 0; j < 4; j++) {
            float s = 0.f;
#pragma unroll
            for (int i = 0; i < 8; i++) s += acc[j][i];
            red[(l0 + j) * 20 + dg] = s;
        }
    }
    __syncthreads();
    if (tid < PB) {
        float s = 0.f;
#pragma unroll
        for (int i = 0; i < 20; i++) s += red[tid * 20 + i];
        mus[tid] = s * (1.0f / 160.0f);
    }
    __syncthreads();
    // pass 2: centered sum of squares
    if (active) {
#pragma unroll
        for (int j = 0; j < 4; j++) {
            float mu = mus[l0 + j];
            float q = 0.f;
#pragma unroll
            for (int i = 0; i < 8; i++) { float d = acc[j][i] - mu; q += d * d; }
            red[(l0 + j) * 20 + dg] = q;
        }
    }
    __syncthreads();
    if (tid < PB) {
        float q = 0.f;
#pragma unroll
        for (int i = 0; i < 20; i++) q += red[tid * 20 + i];
        invs[tid] = rsqrtf(q * (1.0f / 160.0f) + 1e-5f);
    }
    __syncthreads();

    // normalize in registers, store straight to gmem (coalesced across dg)
    if (active) {
#pragma unroll
        for (int j = 0; j < 4; j++) {
            float mu = mus[l0 + j], iv = invs[l0 + j];
            size_t base = ((size_t)(b * L_) + chunk * PB + l0 + j) * D_ + d0;
            float4 o0, o1;
            o0.x = (acc[j][0]-mu)*iv*gs[d0+0] + bs[d0+0];
            o0.y = (acc[j][1]-mu)*iv*gs[d0+1] + bs[d0+1];
            o0.z = (acc[j][2]-mu)*iv*gs[d0+2] + bs[d0+2];
            o0.w = (acc[j][3]-mu)*iv*gs[d0+3] + bs[d0+3];
            o1.x = (acc[j][4]-mu)*iv*gs[d0+4] + bs[d0+4];
            o1.y = (acc[j][5]-mu)*iv*gs[d0+5] + bs[d0+5];
            o1.z = (acc[j][6]-mu)*iv*gs[d0+6] + bs[d0+6];
            o1.w = (acc[j][7]-mu)*iv*gs[d0+7] + bs[d0+7];
            *(float4*)(out + base)     = o0;
            *(float4*)(out + base + 4) = o1;
        }
    }
}

// ---------------------------------------------------------------------------
extern "C" void kernel_launch(void* const* d_in, const int* in_sizes, int n_in,
                              void* d_out, int out_size)
{
    (void)in_sizes; (void)n_in; (void)out_size;
    const float* X        = (const float*)d_in[0];
    const float* Mw       = (const float*)d_in[1];
    const float* w_env    = (const float*)d_in[2];
    const float* w_burst  = (const float*)d_in[3];
    const float* syn      = (const float*)d_in[4];
    const float* w_pre_dw = (const float*)d_in[5];
    const float* w_pre_pw = (const float*)d_in[6];
    const float* w_proj   = (const float*)d_in[7];
    const float* gamma    = (const float*)d_in[8];
    const float* beta     = (const float*)d_in[9];

    float* out     = (float*)d_out;
    float* m_patch = out + (size_t)B_ * L_ * D_;   // h first, then m_patch

    const size_t smem1 = (4 * XB_STRIDE + 4 * S0_STRIDE) * sizeof(float)
                         + 2512 + 268 * sizeof(float);
    const size_t smem2 = (100 * WP_STRIDE + 4 * PB * P_ + PB * 20 + 2 * PB
                          + 2 * D_) * sizeof(float);

    cudaFuncSetAttribute(k_frontend, cudaFuncAttributeMaxDynamicSharedMemorySize,
                         (int)smem1);
    cudaFuncSetAttribute(k_gemm_ln, cudaFuncAttributeMaxDynamicSharedMemorySize,
                         (int)smem2);

    dim3 g1(TILES_PER_B, B_);
    dim3 g2(CHUNKS, B_);
    k_frontend<<<g1, NT1, smem1>>>(X, Mw, w_env, w_burst, syn,
                                   w_pre_dw, w_pre_pw, m_patch);
    k_gemm_ln<<<g2, NT2, smem2>>>(w_proj, gamma, beta, out);
}

// round 12
// speedup vs baseline: 1.9123x; 1.2376x over previous
#include <cuda_runtime.h>
#include <math.h>

// Problem constants
#define B_    64
#define T_    50000
#define C_    4
#define MS_   4
#define D_    160
#define P_    25
#define L_    2000        // T_/P_

// Kernel 1 (frontend) config
#define TILE_T 2500
#define NT1    512
#define TILES_PER_B 20    // 50000/2500
#define XB_STRIDE (TILE_T + 32)   // halo 16 each side
#define S0_STRIDE (TILE_T + 8)    // halo 4 each side

// Kernel 2 (patch GEMM + LN) config
#define PB     80         // patches per block
#define NT2    224        // 200 active GEMM threads (10 patch-grp x 20 d-grp)
#define CHUNKS 25         // 2000/80
#define WP_STRIDE 164     // padded [k][d] row stride
#define XT_STRIDE 84      // padded [k][patch] row stride (16B-aligned rows)

// xs scratch: [b][m][t]  (51.2 MB, static device array — allocation-free)
__device__ float g_xs[(size_t)B_ * MS_ * T_];

__device__ __forceinline__ float gelu_f(float x) {
    return 0.5f * x * (1.0f + erff(x * 0.70710678118654752f));
}

// packed f32x2 helpers (sm_103a)
#define FMA_F32X2(acc, a, b) \
    asm("fma.rn.f32x2 %0, %1, %2, %0;" : "+l"(acc) : "l"(a), "l"(b))
#define DUP_F32X2(out, v) do {                                        \
    unsigned int _u = __float_as_uint(v);                             \
    asm("mov.b64 %0, {%1, %1};" : "=l"(out) : "r"(_u));               \
} while (0)
#define UNPACK_F32X2(lo, hi, in) do {                                 \
    unsigned int _a, _b;                                              \
    asm("mov.b64 {%0, %1}, %2;" : "=r"(_a), "=r"(_b) : "l"(in));      \
    lo = __uint_as_float(_a); hi = __uint_as_float(_b);               \
} while (0)

// ---------------------------------------------------------------------------
// K1: fused frontend (unchanged from R10 — not the bottleneck this round).
// ---------------------------------------------------------------------------
__global__ __launch_bounds__(NT1, 2) void k_frontend(
    const float* __restrict__ X, const float* __restrict__ Mw,
    const float* __restrict__ w_env, const float* __restrict__ w_burst,
    const float* __restrict__ syn, const float* __restrict__ w_pre_dw,
    const float* __restrict__ w_pre_pw, float* __restrict__ m_patch)
{
    extern __shared__ char smem_raw[];
    float* xb  = (float*)smem_raw;                        // [4][XB_STRIDE]
    float* s0  = xb + 4 * XB_STRIDE;                      // [4][S0_STRIDE]
    unsigned char* mk = (unsigned char*)(s0 + 4 * S0_STRIDE); // [2500] pad 2512
    float* wenv  = (float*)(mk + 2512);
    float* wbur  = wenv + 100;
    float* wdw   = wbur + 36;
    float* pw    = wdw + 36;
    float* Wmc   = pw + 16;
    float* smtab = Wmc + 16;

    const int tid  = threadIdx.x;
    const int tile = blockIdx.x;
    const int b    = blockIdx.y;
    const int t0   = tile * TILE_T;

    if (tid < 100)                  wenv[tid]      = w_env[tid];
    if (tid >= 128 && tid < 164)    wbur[tid-128]  = w_burst[tid-128];
    if (tid >= 164 && tid < 200)    wdw[tid-164]   = w_pre_dw[tid-164];
    if (tid >= 200 && tid < 216)    pw[tid-200]    = w_pre_pw[tid-200];
    if (tid >= 216 && tid < 220) {
        int m = tid - 216;
        float w0 = log1pf(expf(syn[m*4+0]));
        float w1 = log1pf(expf(syn[m*4+1]));
        float w2 = log1pf(expf(syn[m*4+2]));
        float w3 = log1pf(expf(syn[m*4+3]));
        float inv = 1.0f / fmaxf(w0+w1+w2+w3, 1e-6f);
        Wmc[m*4+0] = w0*inv; Wmc[m*4+1] = w1*inv;
        Wmc[m*4+2] = w2*inv; Wmc[m*4+3] = w3*inv;
    }

    const float4* X4 = (const float4*)X;
    const float4* M4 = (const float4*)Mw;
    for (int i = tid; i < TILE_T + 32; i += NT1) {
        int gt = t0 - 16 + i;
        float4 v = make_float4(0.f, 0.f, 0.f, 0.f);
        if (gt >= 0 && gt < T_) {
            float4 xv = X4[b * T_ + gt];
            float4 mv = M4[b * T_ + gt];
            v.x = xv.x*mv.x; v.y = xv.y*mv.y; v.z = xv.z*mv.z; v.w = xv.w*mv.w;
            if (i >= 16 && i < 16 + TILE_T)
                mk[i-16] = (unsigned char)((mv.x > 0.f)       | ((mv.y > 0.f) << 1) |
                                           ((mv.z > 0.f) << 2)| ((mv.w > 0.f) << 3));
        }
        xb[0*XB_STRIDE + i] = v.x; xb[1*XB_STRIDE + i] = v.y;
        xb[2*XB_STRIDE + i] = v.z; xb[3*XB_STRIDE + i] = v.w;
    }
    __syncthreads();

    if (tid < 16) {
        int q = tid;
#pragma unroll
        for (int m = 0; m < 4; m++) {
            float s = 0.f;
#pragma unroll
            for (int c = 0; c < 4; c++) s += ((q >> c) & 1) ? Wmc[m*4+c] : 0.f;
            smtab[q*4 + m] = fminf(fmaxf(s, 0.f), 1.f);
        }
    }
    __syncthreads();

    for (int jb = tid; jb < (TILE_T + 8) / 2; jb += NT1) {
        const int j0  = jb * 2;
        const int gS0 = t0 + j0 - 4;
        const bool ok0 = (gS0 >= 0) && (gS0 < T_);
        const bool ok1 = (gS0 + 1 >= 0) && (gS0 + 1 < T_);
        float a0[4] = {0.f,0.f,0.f,0.f}, a1[4] = {0.f,0.f,0.f,0.f};
        if (ok0 | ok1) {
            const bool interior = (t0 + j0 >= 9) && (t0 + j0 + 9 < T_ + 8) &&
                                  (t0 + j0 + 1 < T_);
#pragma unroll
            for (int c = 0; c < 4; c++) {
                const float* xc = xb + c * XB_STRIDE + j0;
                float xw[26];
#pragma unroll
                for (int i = 0; i < 13; i++) {
                    float2 v = *(const float2*)(xc + 2*i);
                    xw[2*i] = v.x; xw[2*i+1] = v.y;
                }
                float ad[10];
                if (interior) {
#pragma unroll
                    for (int i = 0; i < 10; i++)
                        ad[i] = fabsf(xw[8+i] - xw[7+i]);
                } else {
#pragma unroll
                    for (int i = 0; i < 10; i++) {
                        int gt = t0 + j0 + i - 8;
                        ad[i] = (gt >= 1 && gt < T_) ? fabsf(xw[8+i] - xw[7+i]) : 0.f;
                    }
                }
                const float c0 = xw[12], c1 = xw[13];
#pragma unroll
                for (int i = 0; i < 26; i++) xw[i] = fabsf(xw[i]);
                float e0 = 0.f, e1 = 0.f;
#pragma unroll
                for (int k = 0; k < 25; k++) {
                    float w = wenv[c*25+k];
                    e0 += w * xw[k]; e1 += w * xw[k+1];
                }
                float bu0 = 0.f, bu1 = 0.f;
#pragma unroll
                for (int k = 0; k < 9; k++) {
                    float w = wbur[c*9+k];
                    bu0 += w * ad[k]; bu1 += w * ad[k+1];
                }
                float xm0 = 0.9f*e0 + 0.6f*bu0 + 0.2f*c0;
                float xm1 = 0.9f*e1 + 0.6f*bu1 + 0.2f*c1;
#pragma unroll
                for (int m = 0; m < 4; m++) {
                    float w = Wmc[m*4+c];
                    a0[m] += w * xm0; a1[m] += w * xm1;
                }
            }
        }
#pragma unroll
        for (int m = 0; m < 4; m++) {
            s0[m*S0_STRIDE + j0]     = ok0 ? a0[m] : 0.f;
            s0[m*S0_STRIDE + j0 + 1] = ok1 ? a1[m] : 0.f;
        }
    }
    __syncthreads();

    for (int tb = tid; tb < TILE_T / 4; tb += NT1) {
        const int t = tb * 4;
        float s1[4][4];
#pragma unroll
        for (int m = 0; m < 4; m++) {
            const float* sm = s0 + m * S0_STRIDE + t;
            float4 v0 = *(const float4*)(sm);
            float4 v1 = *(const float4*)(sm + 4);
            float4 v2 = *(const float4*)(sm + 8);
            float sw[12] = {v0.x,v0.y,v0.z,v0.w, v1.x,v1.y,v1.z,v1.w,
                            v2.x,v2.y,v2.z,v2.w};
#pragma unroll
            for (int jj = 0; jj < 4; jj++) {
                float a = 0.f;
#pragma unroll
                for (int k = 0; k < 9; k++) a += wdw[m*9+k] * sw[jj+k];
                s1[m][jj] = gelu_f(a);
            }
        }
        const uchar4 q4 = *(const uchar4*)(mk + t);
        const int qq[4] = {q4.x, q4.y, q4.z, q4.w};
#pragma unroll
        for (int o = 0; o < 4; o++) {
            float4 r;
            float* rp = (float*)&r;
#pragma unroll
            for (int jj = 0; jj < 4; jj++) {
                float a = pw[o*4+0]*s1[0][jj] + pw[o*4+1]*s1[1][jj] +
                          pw[o*4+2]*s1[2][jj] + pw[o*4+3]*s1[3][jj];
                rp[jj] = gelu_f(a) * smtab[qq[jj]*4 + o];
            }
            *(float4*)(g_xs + ((size_t)(b*4 + o)) * T_ + t0 + t) = r;
        }
    }

    for (int pl = tid; pl < TILE_T / P_; pl += NT1) {
        int cnt = 0;
#pragma unroll
        for (int p = 0; p < 25; p++) cnt += (mk[pl*25 + p] != 0);
        m_patch[b * L_ + tile * (TILE_T / P_) + pl] = (cnt > 2) ? 1.f : 0.f;
    }
}

// ---------------------------------------------------------------------------
// K2: patch projection GEMM (160 x 80patches, K=100) + LayerNorm(160).
// xs transposed in smem to k-major [k][patch] (stride 84) so 8 consecutive
// patches load as 2x LDS.128 and pair naturally for fma.rn.f32x2 (w scalar
// duplicated). Register tile 8d x 8patches per thread; 200 active threads.
// Per k: 4 LDS + 8 DUP + 32 FFMA2 for 128 MACs. Exact fp32.
// ---------------------------------------------------------------------------
__global__ __launch_bounds__(NT2, 2) void k_gemm_ln(
    const float* __restrict__ w_proj, const float* __restrict__ gamma,
    const float* __restrict__ beta, float* __restrict__ out)
{
    extern __shared__ char smem_raw[];
    float* wp   = (float*)smem_raw;        // [100][WP_STRIDE]  65.6KB
    float* xt   = wp + 100 * WP_STRIDE;    // [100][XT_STRIDE]  33.6KB k-major
    float* red  = xt + 100 * XT_STRIDE;    // [80][20]          6.4KB
    float* mus  = red + PB * 20;           // [80]
    float* invs = mus + PB;                // [80]
    float* gs   = invs + PB;               // [160]
    float* bs   = gs + D_;                 // [160]

    const int tid   = threadIdx.x;
    const int chunk = blockIdx.x;
    const int b     = blockIdx.y;
    const int t0    = chunk * (PB * P_);

    // stage w_proj: global [d][m][p] -> smem [k][d], k = m*25+p
    for (int j = tid; j < D_ * 100; j += NT2) {
        int d = j / 100, k = j - d * 100;
        wp[k * WP_STRIDE + d] = w_proj[j];
    }
    // stage xs transposed: g_xs [m][t], t = l*25+p  ->  xt[(m*25+p)][l]
    for (int i = tid * 4; i < 4 * PB * P_; i += NT2 * 4) {
        int m = i / (PB * P_), t = i - m * (PB * P_);
        float4 v = *(const float4*)(g_xs + ((size_t)(b*4 + m)) * T_ + t0 + t);
        const float vv[4] = {v.x, v.y, v.z, v.w};
#pragma unroll
        for (int q = 0; q < 4; q++) {
            int tq = t + q;
            int l = tq / P_, p = tq - l * P_;
            xt[(m * 25 + p) * XT_STRIDE + l] = vv[q];
        }
    }
    if (tid < D_) { gs[tid] = gamma[tid]; bs[tid] = beta[tid]; }
    __syncthreads();

    // GEMM: 200 active threads, tid = pg*20 + dg; 8 d x 8 patches per thread
    const int pg = tid / 20, dg = tid % 20;
    const int d0 = dg * 8;
    const int l0 = pg * 8;
    const bool active = (tid < 200);

    unsigned long long acc2[4][8];   // [patch-pair j2][d i] -> (l0+2j2, l0+2j2+1)
#pragma unroll
    for (int j = 0; j < 4; j++)
#pragma unroll
        for (int i = 0; i < 8; i++) acc2[j][i] = 0ULL;

    if (active) {
#pragma unroll 2
        for (int k = 0; k < 100; k++) {
            // x: 8 consecutive patches = 4 natural f32x2 pairs
            const ulonglong2 xa = *(const ulonglong2*)(xt + k * XT_STRIDE + l0);
            const ulonglong2 xb2 = *(const ulonglong2*)(xt + k * XT_STRIDE + l0 + 4);
            const unsigned long long xp[4] = {xa.x, xa.y, xb2.x, xb2.y};
            // w: 8 d values
            const float4 w0 = *(const float4*)(wp + k * WP_STRIDE + d0);
            const float4 w1 = *(const float4*)(wp + k * WP_STRIDE + d0 + 4);
            const float wv[8] = {w0.x,w0.y,w0.z,w0.w, w1.x,w1.y,w1.z,w1.w};
#pragma unroll
            for (int i = 0; i < 8; i++) {
                unsigned long long wd;
                DUP_F32X2(wd, wv[i]);
#pragma unroll
                for (int j = 0; j < 4; j++)
                    FMA_F32X2(acc2[j][i], xp[j], wd);
            }
        }
    }

    // unpack: acc[patch jj (0..7)][d i (0..7)]
    float acc[8][8];
#pragma unroll
    for (int j = 0; j < 4; j++)
#pragma unroll
        for (int i = 0; i < 8; i++)
            UNPACK_F32X2(acc[2*j][i], acc[2*j+1][i], acc2[j][i]);

    // pass 1: per-thread sums -> 20 partials per patch
    if (active) {
#pragma unroll
        for (int j = 0; j < 8; j++) {
            float s = 0.f;
#pragma unroll
            for (int i = 0; i < 8; i++) s += acc[j][i];
            red[(l0 + j) * 20 + dg] = s;
        }
    }
    __syncthreads();
    if (tid < PB) {
        float s = 0.f;
#pragma unroll
        for (int i = 0; i < 20; i++) s += red[tid * 20 + i];
        mus[tid] = s * (1.0f / 160.0f);
    }
    __syncthreads();
    // pass 2: centered sum of squares
    if (active) {
#pragma unroll
        for (int j = 0; j < 8; j++) {
            float mu = mus[l0 + j];
            float q = 0.f;
#pragma unroll
            for (int i = 0; i < 8; i++) { float d = acc[j][i] - mu; q += d * d; }
            red[(l0 + j) * 20 + dg] = q;
        }
    }
    __syncthreads();
    if (tid < PB) {
        float q = 0.f;
#pragma unroll
        for (int i = 0; i < 20; i++) q += red[tid * 20 + i];
        invs[tid] = rsqrtf(q * (1.0f / 160.0f) + 1e-5f);
    }
    __syncthreads();

    // normalize in registers, store straight to gmem (coalesced across dg)
    if (active) {
#pragma unroll
        for (int j = 0; j < 8; j++) {
            float mu = mus[l0 + j], iv = invs[l0 + j];
            size_t base = ((size_t)(b * L_) + chunk * PB + l0 + j) * D_ + d0;
            float4 o0, o1;
            o0.x = (acc[j][0]-mu)*iv*gs[d0+0] + bs[d0+0];
            o0.y = (acc[j][1]-mu)*iv*gs[d0+1] + bs[d0+1];
            o0.z = (acc[j][2]-mu)*iv*gs[d0+2] + bs[d0+2];
            o0.w = (acc[j][3]-mu)*iv*gs[d0+3] + bs[d0+3];
            o1.x = (acc[j][4]-mu)*iv*gs[d0+4] + bs[d0+4];
            o1.y = (acc[j][5]-mu)*iv*gs[d0+5] + bs[d0+5];
            o1.z = (acc[j][6]-mu)*iv*gs[d0+6] + bs[d0+6];
            o1.w = (acc[j][7]-mu)*iv*gs[d0+7] + bs[d0+7];
            *(float4*)(out + base)     = o0;
            *(float4*)(out + base + 4) = o1;
        }
    }
}

// ---------------------------------------------------------------------------
extern "C" void kernel_launch(void* const* d_in, const int* in_sizes, int n_in,
                              void* d_out, int out_size)
{
    (void)in_sizes; (void)n_in; (void)out_size;
    const float* X        = (const float*)d_in[0];
    const float* Mw       = (const float*)d_in[1];
    const float* w_env    = (const float*)d_in[2];
    const float* w_burst  = (const float*)d_in[3];
    const float* syn      = (const float*)d_in[4];
    const float* w_pre_dw = (const float*)d_in[5];
    const float* w_pre_pw = (const float*)d_in[6];
    const float* w_proj   = (const float*)d_in[7];
    const float* gamma    = (const float*)d_in[8];
    const float* beta     = (const float*)d_in[9];

    float* out     = (float*)d_out;
    float* m_patch = out + (size_t)B_ * L_ * D_;   // h first, then m_patch

    const size_t smem1 = (4 * XB_STRIDE + 4 * S0_STRIDE) * sizeof(float)
                         + 2512 + 268 * sizeof(float);
    const size_t smem2 = (100 * WP_STRIDE + 100 * XT_STRIDE + PB * 20 + 2 * PB
                          + 2 * D_) * sizeof(float);

    cudaFuncSetAttribute(k_frontend, cudaFuncAttributeMaxDynamicSharedMemorySize,
                         (int)smem1);
    cudaFuncSetAttribute(k_gemm_ln, cudaFuncAttributeMaxDynamicSharedMemorySize,
                         (int)smem2);

    dim3 g1(TILES_PER_B, B_);
    dim3 g2(CHUNKS, B_);
    k_frontend<<<g1, NT1, smem1>>>(X, Mw, w_env, w_burst, syn,
                                   w_pre_dw, w_pre_pw, m_patch);
    k_gemm_ln<<<g2, NT2, smem2>>>(w_proj, gamma, beta, out);
}